// round 14
// baseline (speedup 1.0000x reference)
#include <cuda_runtime.h>
#include <cuda_fp16.h>
#include <math.h>
#include <stdint.h>

#define B_   8
#define S_   512
#define HID_ 768
#define H_   12
#define D_   64
#define BS_  (B_*S_)          // 4096
#define BH_  (B_*H_)          // 96

#define CTX_ELEMS ((size_t)B_*S_*HID_)        // 3,145,728
#define SC_ELEMS  ((size_t)BH_*S_*S_)         // 25,165,824

#define NHID ((size_t)BS_*HID_)               // 3,145,728
#define NW   ((size_t)HID_*HID_)              //   589,824

// Scratch (device globals — no allocation in kernel_launch)
__device__ __half g_qh[BH_*S_*D_];            // q,k,v fp16 (roundoff = tf32's)
__device__ __half g_kh[BH_*S_*D_];
__device__ __half g_vh[BH_*S_*D_];
__device__ float  g_v [BH_*S_*D_];            // V fp32 (tf32-rounded) for O-phase
__device__ __half g_hidH[NHID];               // hidden: fp16 plane
__device__ __half g_WH[3][NW];                // W: fp16 plane (lo term dropped)

__device__ __forceinline__ float to_tf32(float x) {
    float r;
    asm("cvt.rna.tf32.f32 %0, %1;" : "=f"(r) : "f"(x));
    return r;
}

__device__ __forceinline__ void mma_tf32(float* c, const uint32_t* a, const uint32_t* b) {
    asm volatile(
        "mma.sync.aligned.m16n8k8.row.col.f32.tf32.tf32.f32 "
        "{%0,%1,%2,%3}, {%4,%5,%6,%7}, {%8,%9}, {%0,%1,%2,%3};\n"
        : "+f"(c[0]), "+f"(c[1]), "+f"(c[2]), "+f"(c[3])
        : "r"(a[0]), "r"(a[1]), "r"(a[2]), "r"(a[3]), "r"(b[0]), "r"(b[1]));
}

__device__ __forceinline__ void mma_f16(float* c, const uint32_t* a, const uint32_t* b) {
    asm volatile(
        "mma.sync.aligned.m16n8k16.row.col.f32.f16.f16.f32 "
        "{%0,%1,%2,%3}, {%4,%5,%6,%7}, {%8,%9}, {%0,%1,%2,%3};\n"
        : "+f"(c[0]), "+f"(c[1]), "+f"(c[2]), "+f"(c[3])
        : "r"(a[0]), "r"(a[1]), "r"(a[2]), "r"(a[3]), "r"(b[0]), "r"(b[1]));
}

__device__ __forceinline__ uint32_t smem_u32(const void* p) {
    return (uint32_t)__cvta_generic_to_shared(p);
}

__device__ __forceinline__ void cp16(uint32_t dst, const void* src) {
    asm volatile("cp.async.ca.shared.global [%0], [%1], 16;\n" :: "r"(dst), "l"(src));
}

// ---------------------------------------------------------------------------
// Kernel 0: prep. hidden AND W -> fp16 planes (8 elems/thread).
// ---------------------------------------------------------------------------
#define PREP_THREADS ((NHID + 3 * NW) / 8)    // 614,400
#define PREP_BLOCKS  (int)(PREP_THREADS / 256) // 2400

__global__ void __launch_bounds__(256)
split_prep(const float* __restrict__ hid, const float* __restrict__ Wq,
           const float* __restrict__ Wk,  const float* __restrict__ Wv)
{
    size_t i = (size_t)blockIdx.x * 256 + threadIdx.x;
    const float* src;
    __half* dst;
    if (i < NHID / 8) {
        size_t base = i * 8;
        src = hid + base;
        dst = g_hidH + base;
    } else {
        size_t j = i - NHID / 8;
        int w = (int)(j / (NW / 8));
        size_t o8 = (j - (size_t)w * (NW / 8)) * 8;
        src = ((w == 0) ? Wq : ((w == 1) ? Wk : Wv)) + o8;
        dst = g_WH[w] + o8;
    }
    float4 v0 = *(const float4*)src;
    float4 v1 = *(const float4*)(src + 4);
    __half2 o[4];
    o[0] = __half2(__float2half_rn(v0.x), __float2half_rn(v0.y));
    o[1] = __half2(__float2half_rn(v0.z), __float2half_rn(v0.w));
    o[2] = __half2(__float2half_rn(v1.x), __float2half_rn(v1.y));
    o[3] = __half2(__float2half_rn(v1.z), __float2half_rn(v1.w));
    *(uint4*)dst = *(uint4*)o;
}

// ---------------------------------------------------------------------------
// Kernel 1: QKV projection via plain fp16 MMA (single term; A and W lo terms
// dropped, each adds ~2.8e-4 incoherent error — total budget holds).
// Block 128x128, BK=32, double-buffered. 8 warps (2m x 4n), warp 64x32.
// Epilogue: + bias, fp16 q/k/v; V also tf32-fp32 for O-phase.
// ---------------------------------------------------------------------------
__global__ void __launch_bounds__(256, 2)
qkv_mma(const float* __restrict__ bq, const float* __restrict__ bk,
        const float* __restrict__ bv)
{
    const int z = blockIdx.z;
    const __half* Wp  = g_WH[z];
    const float* bias = (z == 0) ? bq : ((z == 1) ? bk : bv);
    __half* outh      = (z == 0) ? g_qh : ((z == 1) ? g_kh : g_vh);

    const int m0 = blockIdx.y * 128;
    const int n0 = blockIdx.x * 128;

    __shared__ __align__(16) uint32_t As[2][128][20];   // 16 k-pair words + pad
    __shared__ __align__(16) uint32_t Bs[2][128][20];

    const int tid  = threadIdx.x;
    const int lane = tid & 31;
    const int wid  = tid >> 5;
    const int gr   = lane >> 2;
    const int gc   = lane & 3;
    const int wm   = (wid & 1) * 64;
    const int wn   = (wid >> 1) * 32;

    float c[4][4][4];
    #pragma unroll
    for (int im = 0; im < 4; im++)
        #pragma unroll
        for (int jn = 0; jn < 4; jn++)
            #pragma unroll
            for (int r = 0; r < 4; r++) c[im][jn][r] = 0.0f;

    // stage = k32 per matrix: 128 rows x 64B = 512 chunks each
    #define LOAD_STAGE(buf, it_)                                                 \
    {                                                                            \
        _Pragma("unroll")                                                        \
        for (int r = 0; r < 2; r++) {                                            \
            int cc = tid + 256 * r; int row = cc >> 2; int sub = cc & 3;         \
            cp16(smem_u32(&As[buf][row][sub * 4]),                               \
                 g_hidH + (size_t)(m0 + row) * HID_ + (it_) * 32 + sub * 8);     \
        }                                                                        \
        _Pragma("unroll")                                                        \
        for (int r = 0; r < 2; r++) {                                            \
            int cc = tid + 256 * r; int row = cc >> 2; int sub = cc & 3;         \
            cp16(smem_u32(&Bs[buf][row][sub * 4]),                               \
                 Wp + (size_t)(n0 + row) * HID_ + (it_) * 32 + sub * 8);         \
        }                                                                        \
        asm volatile("cp.async.commit_group;\n");                                \
    }

    LOAD_STAGE(0, 0)

    const int NIT = HID_ / 32;   // 24 stages of k32
    for (int it = 0; it < NIT; it++) {
        asm volatile("cp.async.wait_group 0;\n");
        __syncthreads();
        if (it + 1 < NIT) { LOAD_STAGE((it + 1) & 1, it + 1) }

        const int buf = it & 1;
        #pragma unroll
        for (int ks = 0; ks < 2; ks++) {       // two k16 steps per stage
            const int kp = 8 * ks + gc;        // k-pair word index
            uint32_t a[4][4], b[4][2];
            #pragma unroll
            for (int im = 0; im < 4; im++) {
                int r = wm + im * 16 + gr;
                a[im][0] = As[buf][r    ][kp    ];
                a[im][1] = As[buf][r + 8][kp    ];
                a[im][2] = As[buf][r    ][kp + 4];
                a[im][3] = As[buf][r + 8][kp + 4];
            }
            #pragma unroll
            for (int jn = 0; jn < 4; jn++) {
                int n = wn + jn * 8 + gr;
                b[jn][0] = Bs[buf][n][kp    ];
                b[jn][1] = Bs[buf][n][kp + 4];
            }
            #pragma unroll
            for (int im = 0; im < 4; im++)
                #pragma unroll
                for (int jn = 0; jn < 4; jn++)
                    mma_f16(c[im][jn], a[im], b[jn]);
        }
        __syncthreads();
    }
    #undef LOAD_STAGE

    // Epilogue: + bias; fp16 q/k/v; V also as tf32-rounded fp32.
    const int h      = (n0 + wn) >> 6;
    const int d_base = (n0 + wn) & 63;
    #pragma unroll
    for (int jn = 0; jn < 4; jn++) {
        int d = d_base + jn * 8 + gc * 2;
        float b0 = bias[n0 + wn + jn * 8 + gc * 2];
        float b1 = bias[n0 + wn + jn * 8 + gc * 2 + 1];
        #pragma unroll
        for (int im = 0; im < 4; im++) {
            int m = m0 + wm + im * 16 + gr;
            int b = m >> 9;
            int s = m & 511;
            size_t base = ((size_t)(b * H_ + h) * S_ + s) * D_ + d;
            float v0 = c[im][jn][0] + b0, v1 = c[im][jn][1] + b1;
            float v2 = c[im][jn][2] + b0, v3 = c[im][jn][3] + b1;
            *(__half2*)(outh + base) =
                __half2(__float2half_rn(v0), __float2half_rn(v1));
            *(__half2*)(outh + base + 8 * D_) =
                __half2(__float2half_rn(v2), __float2half_rn(v3));
            if (z == 2) {
                *(float2*)(g_v + base)          = make_float2(to_tf32(v0), to_tf32(v1));
                *(float2*)(g_v + base + 8 * D_) = make_float2(to_tf32(v2), to_tf32(v3));
            }
        }
    }
}

// ---------------------------------------------------------------------------
// Kernel 2: self-similarity scores (qq, kk, vv) via fp16 m16n8k16 MMA.
// [R13 exact] Block: 64(q) x 128(k), 256 threads (8 warps 2x4).
// grid: (4, 8, 3*96).
// ---------------------------------------------------------------------------
__global__ void __launch_bounds__(256)
scores_sim(const float* __restrict__ mask, float* __restrict__ out_base)
{
    const int z    = blockIdx.z;
    const int type = 1 + z / BH_;       // 1:qq 2:kk 3:vv
    const int bh   = z % BH_;

    const __half* X = (type == 1) ? g_qh : ((type == 2) ? g_kh : g_vh);
    X += (size_t)bh * S_ * D_;

    float* out = out_base + (size_t)type * SC_ELEMS + (size_t)bh * S_ * S_;
    const float* mrow = mask + (size_t)(bh / H_) * S_;

    const int m0 = blockIdx.y * 64;
    const int n0 = blockIdx.x * 128;

    __shared__ __align__(16) uint32_t Xs[64][36];
    __shared__ __align__(16) uint32_t Ys[128][36];

    const int tid = threadIdx.x;

    #pragma unroll
    for (int r = 0; r < 2; r++) {
        int idx = tid + 256 * r;
        int row = idx >> 3;
        int ch  = idx & 7;
        *(uint4*)&Xs[row][ch * 4] =
            *(const uint4*)(X + (size_t)(m0 + row) * D_ + ch * 8);
    }
    #pragma unroll
    for (int r = 0; r < 4; r++) {
        int idx = tid + 256 * r;
        int row = idx >> 3;
        int ch  = idx & 7;
        *(uint4*)&Ys[row][ch * 4] =
            *(const uint4*)(X + (size_t)(n0 + row) * D_ + ch * 8);
    }
    __syncthreads();

    const int lane = tid & 31;
    const int wid  = tid >> 5;
    const int wm   = (wid & 1) * 32;
    const int wn   = (wid >> 1) * 32;
    const int gr   = lane >> 2;
    const int gc   = lane & 3;

    float c[2][4][4];
    #pragma unroll
    for (int im = 0; im < 2; im++)
        #pragma unroll
        for (int jn = 0; jn < 4; jn++)
            #pragma unroll
            for (int r = 0; r < 4; r++) c[im][jn][r] = 0.0f;

    #pragma unroll
    for (int st = 0; st < 4; st++) {
        const int kp = st * 8 + gc;
        uint32_t a[2][4], b[4][2];
        #pragma unroll
        for (int im = 0; im < 2; im++) {
            int r0 = wm + im * 16 + gr;
            a[im][0] = Xs[r0    ][kp    ];
            a[im][1] = Xs[r0 + 8][kp    ];
            a[im][2] = Xs[r0    ][kp + 4];
            a[im][3] = Xs[r0 + 8][kp + 4];
        }
        #pragma unroll
        for (int jn = 0; jn < 4; jn++) {
            int n = wn + jn * 8 + gr;
            b[jn][0] = Ys[n][kp    ];
            b[jn][1] = Ys[n][kp + 4];
        }
        #pragma unroll
        for (int im = 0; im < 2; im++)
            #pragma unroll
            for (int jn = 0; jn < 4; jn++)
                mma_f16(c[im][jn], a[im], b[jn]);
    }

    #pragma unroll
    for (int im = 0; im < 2; im++) {
        #pragma unroll
        for (int jn = 0; jn < 4; jn++) {
            int row = m0 + wm + im * 16 + gr;
            int col = n0 + wn + jn * 8 + gc * 2;
            float mv0 = mrow[col], mv1 = mrow[col + 1];
            float2 o0 = make_float2(c[im][jn][0] * 0.125f + mv0,
                                    c[im][jn][1] * 0.125f + mv1);
            float2 o1 = make_float2(c[im][jn][2] * 0.125f + mv0,
                                    c[im][jn][3] * 0.125f + mv1);
            *(float2*)(out + (size_t)row * S_ + col)       = o0;
            *(float2*)(out + (size_t)(row + 8) * S_ + col) = o1;
        }
    }
}

// ---------------------------------------------------------------------------
// Kernel 3: fused qk-scores + softmax + P@V. [R13 exact]
// S-phase fp16, O-phase tf32. 128 threads = 4 warps. grid: (8, 96).
// ---------------------------------------------------------------------------
__global__ void __launch_bounds__(128)
flash_attn(const float* __restrict__ mask, float* __restrict__ sout_base,
           float* __restrict__ ctx)
{
    const int bh = blockIdx.y;
    const int q0 = blockIdx.x * 64;
    const int b  = bh / H_;
    const int h  = bh - b * H_;
    const __half* Qp = g_qh + (size_t)bh * S_ * D_;
    const __half* Kp = g_kh + (size_t)bh * S_ * D_;
    const float*  Vp = g_v  + (size_t)bh * S_ * D_;
    float* sout = sout_base + (size_t)bh * S_ * S_;
    const float* mrow = mask + (size_t)b * S_;

    __shared__ __align__(16) float QPs[64][68];
    __shared__ __align__(16) uint32_t Ku[64][36];
    __shared__ float Vs[64][72];

    uint32_t* QPu = (uint32_t*)&QPs[0][0];

    const int tid  = threadIdx.x;
    const int lane = tid & 31;
    const int w    = tid >> 5;
    const int gr   = lane >> 2;
    const int gc   = lane & 3;

    #pragma unroll
    for (int r = 0; r < 4; r++) {
        int idx = tid + 128 * r;
        int row = idx >> 3;
        int ch  = idx & 7;
        *(uint4*)&QPu[row * 36 + ch * 4] =
            *(const uint4*)(Qp + (size_t)(q0 + row) * D_ + ch * 8);
    }
    __syncthreads();

    uint32_t aq[4][4];
    #pragma unroll
    for (int st = 0; st < 4; st++) {
        int kp = st * 8 + gc;
        int r0 = w * 16 + gr;
        aq[st][0] = QPu[ r0      * 36 + kp    ];
        aq[st][1] = QPu[(r0 + 8) * 36 + kp    ];
        aq[st][2] = QPu[ r0      * 36 + kp + 4];
        aq[st][3] = QPu[(r0 + 8) * 36 + kp + 4];
    }

    float o[8][4];
    #pragma unroll
    for (int jd = 0; jd < 8; jd++)
        #pragma unroll
        for (int r = 0; r < 4; r++) o[jd][r] = 0.0f;

    float m0 = -1e30f, m1 = -1e30f, l0 = 0.0f, l1 = 0.0f;
    const int rowg = q0 + w * 16 + gr;

    for (int kt = 0; kt < 8; kt++) {
        #pragma unroll
        for (int r = 0; r < 4; r++) {
            int idx = tid + 128 * r;
            int row = idx >> 3;
            int ch  = idx & 7;
            *(uint4*)&Ku[row][ch * 4] =
                *(const uint4*)(Kp + (size_t)(kt*64 + row) * D_ + ch * 8);
        }
        #pragma unroll
        for (int r = 0; r < 8; r++) {
            int idx = tid + 128 * r;
            int row = idx >> 4;
            int q   = idx & 15;
            *(float4*)&Vs[row][q * 4] =
                *(const float4*)(Vp + (size_t)(kt*64 + row) * D_ + q * 4);
        }
        __syncthreads();

        float s[8][4];
        #pragma unroll
        for (int jn = 0; jn < 8; jn++) {
            #pragma unroll
            for (int r = 0; r < 4; r++) s[jn][r] = 0.0f;
            #pragma unroll
            for (int st = 0; st < 4; st++) {
                int kp = st * 8 + gc;
                uint32_t bv[2];
                bv[0] = Ku[jn*8 + gr][kp    ];
                bv[1] = Ku[jn*8 + gr][kp + 4];
                mma_f16(s[jn], aq[st], bv);
            }
        }

        float mx0 = -1e30f, mx1 = -1e30f;
        #pragma unroll
        for (int jn = 0; jn < 8; jn++) {
            int col = kt*64 + jn*8 + gc*2;
            float mv0 = mrow[col], mv1 = mrow[col + 1];
            s[jn][0] = s[jn][0]*0.125f + mv0;  s[jn][1] = s[jn][1]*0.125f + mv1;
            s[jn][2] = s[jn][2]*0.125f + mv0;  s[jn][3] = s[jn][3]*0.125f + mv1;
            *(float2*)(sout + (size_t)rowg       * S_ + col) = make_float2(s[jn][0], s[jn][1]);
            *(float2*)(sout + (size_t)(rowg + 8) * S_ + col) = make_float2(s[jn][2], s[jn][3]);
            mx0 = fmaxf(mx0, fmaxf(s[jn][0], s[jn][1]));
            mx1 = fmaxf(mx1, fmaxf(s[jn][2], s[jn][3]));
        }
        mx0 = fmaxf(mx0, __shfl_xor_sync(0xffffffffu, mx0, 1));
        mx0 = fmaxf(mx0, __shfl_xor_sync(0xffffffffu, mx0, 2));
        mx1 = fmaxf(mx1, __shfl_xor_sync(0xffffffffu, mx1, 1));
        mx1 = fmaxf(mx1, __shfl_xor_sync(0xffffffffu, mx1, 2));

        float mn0 = fmaxf(m0, mx0), mn1 = fmaxf(m1, mx1);
        float sc0 = __expf(m0 - mn0), sc1 = __expf(m1 - mn1);

        float ps0 = 0.0f, ps1 = 0.0f;
        #pragma unroll
        for (int jn = 0; jn < 8; jn++) {
            float p0 = __expf(s[jn][0] - mn0), p1 = __expf(s[jn][1] - mn0);
            float p2 = __expf(s[jn][2] - mn1), p3 = __expf(s[jn][3] - mn1);
            ps0 += p0 + p1;  ps1 += p2 + p3;
            int col = jn*8 + gc*2;
            int r0  = w*16 + gr;
            *(float2*)&QPs[r0    ][col] = make_float2(to_tf32(p0), to_tf32(p1));
            *(float2*)&QPs[r0 + 8][col] = make_float2(to_tf32(p2), to_tf32(p3));
        }
        ps0 += __shfl_xor_sync(0xffffffffu, ps0, 1);
        ps0 += __shfl_xor_sync(0xffffffffu, ps0, 2);
        ps1 += __shfl_xor_sync(0xffffffffu, ps1, 1);
        ps1 += __shfl_xor_sync(0xffffffffu, ps1, 2);
        l0 = l0 * sc0 + ps0;  l1 = l1 * sc1 + ps1;
        m0 = mn0;  m1 = mn1;

        #pragma unroll
        for (int jd = 0; jd < 8; jd++) {
            o[jd][0] *= sc0;  o[jd][1] *= sc0;
            o[jd][2] *= sc1;  o[jd][3] *= sc1;
        }
        __syncwarp();

        #pragma unroll
        for (int ks = 0; ks < 8; ks++) {
            uint32_t ap[4];
            int r0 = w*16 + gr;
            ap[0] = __float_as_uint(QPs[r0    ][8*ks + gc    ]);
            ap[1] = __float_as_uint(QPs[r0 + 8][8*ks + gc    ]);
            ap[2] = __float_as_uint(QPs[r0    ][8*ks + gc + 4]);
            ap[3] = __float_as_uint(QPs[r0 + 8][8*ks + gc + 4]);
            #pragma unroll
            for (int jd = 0; jd < 8; jd++) {
                uint32_t bv[2];
                bv[0] = __float_as_uint(Vs[8*ks + gc    ][jd*8 + gr]);
                bv[1] = __float_as_uint(Vs[8*ks + gc + 4][jd*8 + gr]);
                mma_tf32(o[jd], ap, bv);
            }
        }
        __syncthreads();
    }

    float i0 = 1.0f / l0, i1 = 1.0f / l1;
    #pragma unroll
    for (int jd = 0; jd < 8; jd++) {
        int d = jd*8 + gc*2;
        float* op = ctx + ((size_t)(b * S_ + rowg) * HID_ + h * D_ + d);
        *(float2*)op              = make_float2(o[jd][0] * i0, o[jd][1] * i0);
        *(float2*)(op + 8 * HID_) = make_float2(o[jd][2] * i1, o[jd][3] * i1);
    }
}

// ---------------------------------------------------------------------------
extern "C" void kernel_launch(void* const* d_in, const int* in_sizes, int n_in,
                              void* d_out, int out_size)
{
    const float* hid  = (const float*)d_in[0];
    const float* mask = (const float*)d_in[1];
    const float* Wq   = (const float*)d_in[2];
    const float* bq   = (const float*)d_in[3];
    const float* Wk   = (const float*)d_in[4];
    const float* bk   = (const float*)d_in[5];
    const float* Wv   = (const float*)d_in[6];
    const float* bv   = (const float*)d_in[7];
    float* out = (float*)d_out;

    // 0) prep: hidden + W -> fp16 planes
    split_prep<<<PREP_BLOCKS, 256>>>(hid, Wq, Wk, Wv);

    // 1) Q,K,V projections (plain fp16 MMA; fp16 q/k/v + fp32 V)
    qkv_mma<<<dim3(HID_ / 128, BS_ / 128, 3), 256>>>(bq, bk, bv);

    // 2) qq / kk / vv self-similarity scores (fp16 MMA)
    scores_sim<<<dim3(S_ / 128, S_ / 64, 3 * BH_), 256>>>(mask, out + CTX_ELEMS);

    // 3) fused qk scores + softmax + P@V -> scores(qk) region + ctx
    flash_attn<<<dim3(S_ / 64, BH_), 128>>>(mask, out + CTX_ELEMS, out);
}

// round 15
// speedup vs baseline: 1.5207x; 1.5207x over previous
#include <cuda_runtime.h>
#include <cuda_fp16.h>
#include <math.h>
#include <stdint.h>

#define B_   8
#define S_   512
#define HID_ 768
#define H_   12
#define D_   64
#define BS_  (B_*S_)          // 4096
#define BH_  (B_*H_)          // 96

#define CTX_ELEMS ((size_t)B_*S_*HID_)        // 3,145,728
#define SC_ELEMS  ((size_t)BH_*S_*S_)         // 25,165,824

#define NHID ((size_t)BS_*HID_)               // 3,145,728
#define NW   ((size_t)HID_*HID_)              //   589,824

// Scratch (device globals — no allocation in kernel_launch)
__device__ __half g_qh[BH_*S_*D_];            // q,k,v fp16 (roundoff = tf32's)
__device__ __half g_kh[BH_*S_*D_];
__device__ __half g_vh[BH_*S_*D_];
__device__ float  g_v [BH_*S_*D_];            // V fp32 (tf32-rounded) for O-phase
__device__ __half g_hidH[NHID];               // hidden: fp16 plane
__device__ __half g_WH[3][NW];                // W: fp16 plane (lo term dropped)

__device__ __forceinline__ float to_tf32(float x) {
    float r;
    asm("cvt.rna.tf32.f32 %0, %1;" : "=f"(r) : "f"(x));
    return r;
}

__device__ __forceinline__ void mma_tf32(float* c, const uint32_t* a, const uint32_t* b) {
    asm volatile(
        "mma.sync.aligned.m16n8k8.row.col.f32.tf32.tf32.f32 "
        "{%0,%1,%2,%3}, {%4,%5,%6,%7}, {%8,%9}, {%0,%1,%2,%3};\n"
        : "+f"(c[0]), "+f"(c[1]), "+f"(c[2]), "+f"(c[3])
        : "r"(a[0]), "r"(a[1]), "r"(a[2]), "r"(a[3]), "r"(b[0]), "r"(b[1]));
}

__device__ __forceinline__ void mma_f16(float* c, const uint32_t* a, const uint32_t* b) {
    asm volatile(
        "mma.sync.aligned.m16n8k16.row.col.f32.f16.f16.f32 "
        "{%0,%1,%2,%3}, {%4,%5,%6,%7}, {%8,%9}, {%0,%1,%2,%3};\n"
        : "+f"(c[0]), "+f"(c[1]), "+f"(c[2]), "+f"(c[3])
        : "r"(a[0]), "r"(a[1]), "r"(a[2]), "r"(a[3]), "r"(b[0]), "r"(b[1]));
}

__device__ __forceinline__ uint32_t smem_u32(const void* p) {
    return (uint32_t)__cvta_generic_to_shared(p);
}

__device__ __forceinline__ void cp16(uint32_t dst, const void* src) {
    asm volatile("cp.async.ca.shared.global [%0], [%1], 16;\n" :: "r"(dst), "l"(src));
}

// ---------------------------------------------------------------------------
// Kernel 0: prep. hidden AND W -> fp16 planes (8 elems/thread).
// ---------------------------------------------------------------------------
#define PREP_THREADS ((NHID + 3 * NW) / 8)    // 614,400
#define PREP_BLOCKS  (int)(PREP_THREADS / 256) // 2400

__global__ void __launch_bounds__(256)
split_prep(const float* __restrict__ hid, const float* __restrict__ Wq,
           const float* __restrict__ Wk,  const float* __restrict__ Wv)
{
    size_t i = (size_t)blockIdx.x * 256 + threadIdx.x;
    const float* src;
    __half* dst;
    if (i < NHID / 8) {
        size_t base = i * 8;
        src = hid + base;
        dst = g_hidH + base;
    } else {
        size_t j = i - NHID / 8;
        int w = (int)(j / (NW / 8));
        size_t o8 = (j - (size_t)w * (NW / 8)) * 8;
        src = ((w == 0) ? Wq : ((w == 1) ? Wk : Wv)) + o8;
        dst = g_WH[w] + o8;
    }
    float4 v0 = *(const float4*)src;
    float4 v1 = *(const float4*)(src + 4);
    __half2 o[4];
    o[0] = __half2(__float2half_rn(v0.x), __float2half_rn(v0.y));
    o[1] = __half2(__float2half_rn(v0.z), __float2half_rn(v0.w));
    o[2] = __half2(__float2half_rn(v1.x), __float2half_rn(v1.y));
    o[3] = __half2(__float2half_rn(v1.z), __float2half_rn(v1.w));
    *(uint4*)dst = *(uint4*)o;
}

// ---------------------------------------------------------------------------
// Kernel 1: QKV projection via plain fp16 MMA (single term; A and W lo terms
// dropped, each adds ~2.8e-4 incoherent error — total budget holds).
// Block 128x128, BK=32, double-buffered. 8 warps (2m x 4n), warp 64x32.
// Epilogue: + bias, fp16 q/k/v; V also tf32-fp32 for O-phase.
// ---------------------------------------------------------------------------
__global__ void __launch_bounds__(256, 2)
qkv_mma(const float* __restrict__ bq, const float* __restrict__ bk,
        const float* __restrict__ bv)
{
    const int z = blockIdx.z;
    const __half* Wp  = g_WH[z];
    const float* bias = (z == 0) ? bq : ((z == 1) ? bk : bv);
    __half* outh      = (z == 0) ? g_qh : ((z == 1) ? g_kh : g_vh);

    const int m0 = blockIdx.y * 128;
    const int n0 = blockIdx.x * 128;

    __shared__ __align__(16) uint32_t As[2][128][20];   // 16 k-pair words + pad
    __shared__ __align__(16) uint32_t Bs[2][128][20];

    const int tid  = threadIdx.x;
    const int lane = tid & 31;
    const int wid  = tid >> 5;
    const int gr   = lane >> 2;
    const int gc   = lane & 3;
    const int wm   = (wid & 1) * 64;
    const int wn   = (wid >> 1) * 32;

    float c[4][4][4];
    #pragma unroll
    for (int im = 0; im < 4; im++)
        #pragma unroll
        for (int jn = 0; jn < 4; jn++)
            #pragma unroll
            for (int r = 0; r < 4; r++) c[im][jn][r] = 0.0f;

    // stage = k32 per matrix: 128 rows x 64B = 512 chunks each
    #define LOAD_STAGE(buf, it_)                                                 \
    {                                                                            \
        _Pragma("unroll")                                                        \
        for (int r = 0; r < 2; r++) {                                            \
            int cc = tid + 256 * r; int row = cc >> 2; int sub = cc & 3;         \
            cp16(smem_u32(&As[buf][row][sub * 4]),                               \
                 g_hidH + (size_t)(m0 + row) * HID_ + (it_) * 32 + sub * 8);     \
        }                                                                        \
        _Pragma("unroll")                                                        \
        for (int r = 0; r < 2; r++) {                                            \
            int cc = tid + 256 * r; int row = cc >> 2; int sub = cc & 3;         \
            cp16(smem_u32(&Bs[buf][row][sub * 4]),                               \
                 Wp + (size_t)(n0 + row) * HID_ + (it_) * 32 + sub * 8);         \
        }                                                                        \
        asm volatile("cp.async.commit_group;\n");                                \
    }

    LOAD_STAGE(0, 0)

    const int NIT = HID_ / 32;   // 24 stages of k32
    for (int it = 0; it < NIT; it++) {
        asm volatile("cp.async.wait_group 0;\n");
        __syncthreads();
        if (it + 1 < NIT) { LOAD_STAGE((it + 1) & 1, it + 1) }

        const int buf = it & 1;
        #pragma unroll
        for (int ks = 0; ks < 2; ks++) {       // two k16 steps per stage
            const int kp = 8 * ks + gc;        // k-pair word index
            uint32_t a[4][4], b[4][2];
            #pragma unroll
            for (int im = 0; im < 4; im++) {
                int r = wm + im * 16 + gr;
                a[im][0] = As[buf][r    ][kp    ];
                a[im][1] = As[buf][r + 8][kp    ];
                a[im][2] = As[buf][r    ][kp + 4];
                a[im][3] = As[buf][r + 8][kp + 4];
            }
            #pragma unroll
            for (int jn = 0; jn < 4; jn++) {
                int n = wn + jn * 8 + gr;
                b[jn][0] = Bs[buf][n][kp    ];
                b[jn][1] = Bs[buf][n][kp + 4];
            }
            #pragma unroll
            for (int im = 0; im < 4; im++)
                #pragma unroll
                for (int jn = 0; jn < 4; jn++)
                    mma_f16(c[im][jn], a[im], b[jn]);
        }
        __syncthreads();
    }
    #undef LOAD_STAGE

    // Epilogue: + bias; fp16 q/k/v; V also as tf32-rounded fp32.
    const int h      = (n0 + wn) >> 6;
    const int d_base = (n0 + wn) & 63;
    #pragma unroll
    for (int jn = 0; jn < 4; jn++) {
        int d = d_base + jn * 8 + gc * 2;
        float b0 = bias[n0 + wn + jn * 8 + gc * 2];
        float b1 = bias[n0 + wn + jn * 8 + gc * 2 + 1];
        #pragma unroll
        for (int im = 0; im < 4; im++) {
            int m = m0 + wm + im * 16 + gr;
            int b = m >> 9;
            int s = m & 511;
            size_t base = ((size_t)(b * H_ + h) * S_ + s) * D_ + d;
            float v0 = c[im][jn][0] + b0, v1 = c[im][jn][1] + b1;
            float v2 = c[im][jn][2] + b0, v3 = c[im][jn][3] + b1;
            *(__half2*)(outh + base) =
                __half2(__float2half_rn(v0), __float2half_rn(v1));
            *(__half2*)(outh + base + 8 * D_) =
                __half2(__float2half_rn(v2), __float2half_rn(v3));
            if (z == 2) {
                *(float2*)(g_v + base)          = make_float2(to_tf32(v0), to_tf32(v1));
                *(float2*)(g_v + base + 8 * D_) = make_float2(to_tf32(v2), to_tf32(v3));
            }
        }
    }
}

// ---------------------------------------------------------------------------
// Kernel 2: self-similarity scores (qq, kk, vv) via fp16 m16n8k16 MMA.
// Block: 64(q) x 128(k), 256 threads (8 warps 2x4). grid: (4, 8, 3*96).
// ---------------------------------------------------------------------------
__global__ void __launch_bounds__(256)
scores_sim(const float* __restrict__ mask, float* __restrict__ out_base)
{
    const int z    = blockIdx.z;
    const int type = 1 + z / BH_;       // 1:qq 2:kk 3:vv
    const int bh   = z % BH_;

    const __half* X = (type == 1) ? g_qh : ((type == 2) ? g_kh : g_vh);
    X += (size_t)bh * S_ * D_;

    float* out = out_base + (size_t)type * SC_ELEMS + (size_t)bh * S_ * S_;
    const float* mrow = mask + (size_t)(bh / H_) * S_;

    const int m0 = blockIdx.y * 64;
    const int n0 = blockIdx.x * 128;

    __shared__ __align__(16) uint32_t Xs[64][36];
    __shared__ __align__(16) uint32_t Ys[128][36];

    const int tid = threadIdx.x;

    #pragma unroll
    for (int r = 0; r < 2; r++) {
        int idx = tid + 256 * r;
        int row = idx >> 3;
        int ch  = idx & 7;
        *(uint4*)&Xs[row][ch * 4] =
            *(const uint4*)(X + (size_t)(m0 + row) * D_ + ch * 8);
    }
    #pragma unroll
    for (int r = 0; r < 4; r++) {
        int idx = tid + 256 * r;
        int row = idx >> 3;
        int ch  = idx & 7;
        *(uint4*)&Ys[row][ch * 4] =
            *(const uint4*)(X + (size_t)(n0 + row) * D_ + ch * 8);
    }
    __syncthreads();

    const int lane = tid & 31;
    const int wid  = tid >> 5;
    const int wm   = (wid & 1) * 32;
    const int wn   = (wid >> 1) * 32;
    const int gr   = lane >> 2;
    const int gc   = lane & 3;

    float c[2][4][4];
    #pragma unroll
    for (int im = 0; im < 2; im++)
        #pragma unroll
        for (int jn = 0; jn < 4; jn++)
            #pragma unroll
            for (int r = 0; r < 4; r++) c[im][jn][r] = 0.0f;

    #pragma unroll
    for (int st = 0; st < 4; st++) {
        const int kp = st * 8 + gc;
        uint32_t a[2][4], b[4][2];
        #pragma unroll
        for (int im = 0; im < 2; im++) {
            int r0 = wm + im * 16 + gr;
            a[im][0] = Xs[r0    ][kp    ];
            a[im][1] = Xs[r0 + 8][kp    ];
            a[im][2] = Xs[r0    ][kp + 4];
            a[im][3] = Xs[r0 + 8][kp + 4];
        }
        #pragma unroll
        for (int jn = 0; jn < 4; jn++) {
            int n = wn + jn * 8 + gr;
            b[jn][0] = Ys[n][kp    ];
            b[jn][1] = Ys[n][kp + 4];
        }
        #pragma unroll
        for (int im = 0; im < 2; im++)
            #pragma unroll
            for (int jn = 0; jn < 4; jn++)
                mma_f16(c[im][jn], a[im], b[jn]);
    }

    #pragma unroll
    for (int im = 0; im < 2; im++) {
        #pragma unroll
        for (int jn = 0; jn < 4; jn++) {
            int row = m0 + wm + im * 16 + gr;
            int col = n0 + wn + jn * 8 + gc * 2;
            float mv0 = mrow[col], mv1 = mrow[col + 1];
            float2 o0 = make_float2(c[im][jn][0] * 0.125f + mv0,
                                    c[im][jn][1] * 0.125f + mv1);
            float2 o1 = make_float2(c[im][jn][2] * 0.125f + mv0,
                                    c[im][jn][3] * 0.125f + mv1);
            *(float2*)(out + (size_t)row * S_ + col)       = o0;
            *(float2*)(out + (size_t)(row + 8) * S_ + col) = o1;
        }
    }
}

// ---------------------------------------------------------------------------
// Kernel 3: fused qk-scores + softmax + P@V.
// S-phase fp16, O-phase tf32. 128 threads = 4 warps. grid: (8, 96).
// ---------------------------------------------------------------------------
__global__ void __launch_bounds__(128)
flash_attn(const float* __restrict__ mask, float* __restrict__ sout_base,
           float* __restrict__ ctx)
{
    const int bh = blockIdx.y;
    const int q0 = blockIdx.x * 64;
    const int b  = bh / H_;
    const int h  = bh - b * H_;
    const __half* Qp = g_qh + (size_t)bh * S_ * D_;
    const __half* Kp = g_kh + (size_t)bh * S_ * D_;
    const float*  Vp = g_v  + (size_t)bh * S_ * D_;
    float* sout = sout_base + (size_t)bh * S_ * S_;
    const float* mrow = mask + (size_t)b * S_;

    __shared__ __align__(16) float QPs[64][68];
    __shared__ __align__(16) uint32_t Ku[64][36];
    __shared__ float Vs[64][72];

    uint32_t* QPu = (uint32_t*)&QPs[0][0];

    const int tid  = threadIdx.x;
    const int lane = tid & 31;
    const int w    = tid >> 5;
    const int gr   = lane >> 2;
    const int gc   = lane & 3;

    #pragma unroll
    for (int r = 0; r < 4; r++) {
        int idx = tid + 128 * r;
        int row = idx >> 3;
        int ch  = idx & 7;
        *(uint4*)&QPu[row * 36 + ch * 4] =
            *(const uint4*)(Qp + (size_t)(q0 + row) * D_ + ch * 8);
    }
    __syncthreads();

    uint32_t aq[4][4];
    #pragma unroll
    for (int st = 0; st < 4; st++) {
        int kp = st * 8 + gc;
        int r0 = w * 16 + gr;
        aq[st][0] = QPu[ r0      * 36 + kp    ];
        aq[st][1] = QPu[(r0 + 8) * 36 + kp    ];
        aq[st][2] = QPu[ r0      * 36 + kp + 4];
        aq[st][3] = QPu[(r0 + 8) * 36 + kp + 4];
    }

    float o[8][4];
    #pragma unroll
    for (int jd = 0; jd < 8; jd++)
        #pragma unroll
        for (int r = 0; r < 4; r++) o[jd][r] = 0.0f;

    float m0 = -1e30f, m1 = -1e30f, l0 = 0.0f, l1 = 0.0f;
    const int rowg = q0 + w * 16 + gr;

    for (int kt = 0; kt < 8; kt++) {
        #pragma unroll
        for (int r = 0; r < 4; r++) {
            int idx = tid + 128 * r;
            int row = idx >> 3;
            int ch  = idx & 7;
            *(uint4*)&Ku[row][ch * 4] =
                *(const uint4*)(Kp + (size_t)(kt*64 + row) * D_ + ch * 8);
        }
        #pragma unroll
        for (int r = 0; r < 8; r++) {
            int idx = tid + 128 * r;
            int row = idx >> 4;
            int q   = idx & 15;
            *(float4*)&Vs[row][q * 4] =
                *(const float4*)(Vp + (size_t)(kt*64 + row) * D_ + q * 4);
        }
        __syncthreads();

        float s[8][4];
        #pragma unroll
        for (int jn = 0; jn < 8; jn++) {
            #pragma unroll
            for (int r = 0; r < 4; r++) s[jn][r] = 0.0f;
            #pragma unroll
            for (int st = 0; st < 4; st++) {
                int kp = st * 8 + gc;
                uint32_t bv[2];
                bv[0] = Ku[jn*8 + gr][kp    ];
                bv[1] = Ku[jn*8 + gr][kp + 4];
                mma_f16(s[jn], aq[st], bv);
            }
        }

        float mx0 = -1e30f, mx1 = -1e30f;
        #pragma unroll
        for (int jn = 0; jn < 8; jn++) {
            int col = kt*64 + jn*8 + gc*2;
            float mv0 = mrow[col], mv1 = mrow[col + 1];
            s[jn][0] = s[jn][0]*0.125f + mv0;  s[jn][1] = s[jn][1]*0.125f + mv1;
            s[jn][2] = s[jn][2]*0.125f + mv0;  s[jn][3] = s[jn][3]*0.125f + mv1;
            *(float2*)(sout + (size_t)rowg       * S_ + col) = make_float2(s[jn][0], s[jn][1]);
            *(float2*)(sout + (size_t)(rowg + 8) * S_ + col) = make_float2(s[jn][2], s[jn][3]);
            mx0 = fmaxf(mx0, fmaxf(s[jn][0], s[jn][1]));
            mx1 = fmaxf(mx1, fmaxf(s[jn][2], s[jn][3]));
        }
        mx0 = fmaxf(mx0, __shfl_xor_sync(0xffffffffu, mx0, 1));
        mx0 = fmaxf(mx0, __shfl_xor_sync(0xffffffffu, mx0, 2));
        mx1 = fmaxf(mx1, __shfl_xor_sync(0xffffffffu, mx1, 1));
        mx1 = fmaxf(mx1, __shfl_xor_sync(0xffffffffu, mx1, 2));

        float mn0 = fmaxf(m0, mx0), mn1 = fmaxf(m1, mx1);
        float sc0 = __expf(m0 - mn0), sc1 = __expf(m1 - mn1);

        float ps0 = 0.0f, ps1 = 0.0f;
        #pragma unroll
        for (int jn = 0; jn < 8; jn++) {
            float p0 = __expf(s[jn][0] - mn0), p1 = __expf(s[jn][1] - mn0);
            float p2 = __expf(s[jn][2] - mn1), p3 = __expf(s[jn][3] - mn1);
            ps0 += p0 + p1;  ps1 += p2 + p3;
            int col = jn*8 + gc*2;
            int r0  = w*16 + gr;
            *(float2*)&QPs[r0    ][col] = make_float2(to_tf32(p0), to_tf32(p1));
            *(float2*)&QPs[r0 + 8][col] = make_float2(to_tf32(p2), to_tf32(p3));
        }
        ps0 += __shfl_xor_sync(0xffffffffu, ps0, 1);
        ps0 += __shfl_xor_sync(0xffffffffu, ps0, 2);
        ps1 += __shfl_xor_sync(0xffffffffu, ps1, 1);
        ps1 += __shfl_xor_sync(0xffffffffu, ps1, 2);
        l0 = l0 * sc0 + ps0;  l1 = l1 * sc1 + ps1;
        m0 = mn0;  m1 = mn1;

        #pragma unroll
        for (int jd = 0; jd < 8; jd++) {
            o[jd][0] *= sc0;  o[jd][1] *= sc0;
            o[jd][2] *= sc1;  o[jd][3] *= sc1;
        }
        __syncwarp();

        #pragma unroll
        for (int ks = 0; ks < 8; ks++) {
            uint32_t ap[4];
            int r0 = w*16 + gr;
            ap[0] = __float_as_uint(QPs[r0    ][8*ks + gc    ]);
            ap[1] = __float_as_uint(QPs[r0 + 8][8*ks + gc    ]);
            ap[2] = __float_as_uint(QPs[r0    ][8*ks + gc + 4]);
            ap[3] = __float_as_uint(QPs[r0 + 8][8*ks + gc + 4]);
            #pragma unroll
            for (int jd = 0; jd < 8; jd++) {
                uint32_t bv[2];
                bv[0] = __float_as_uint(Vs[8*ks + gc    ][jd*8 + gr]);
                bv[1] = __float_as_uint(Vs[8*ks + gc + 4][jd*8 + gr]);
                mma_tf32(o[jd], ap, bv);
            }
        }
        __syncthreads();
    }

    float i0 = 1.0f / l0, i1 = 1.0f / l1;
    #pragma unroll
    for (int jd = 0; jd < 8; jd++) {
        int d = jd*8 + gc*2;
        float* op = ctx + ((size_t)(b * S_ + rowg) * HID_ + h * D_ + d);
        *(float2*)op              = make_float2(o[jd][0] * i0, o[jd][1] * i0);
        *(float2*)(op + 8 * HID_) = make_float2(o[jd][2] * i1, o[jd][3] * i1);
    }
}

// ---------------------------------------------------------------------------
extern "C" void kernel_launch(void* const* d_in, const int* in_sizes, int n_in,
                              void* d_out, int out_size)
{
    const float* hid  = (const float*)d_in[0];
    const float* mask = (const float*)d_in[1];
    const float* Wq   = (const float*)d_in[2];
    const float* bq   = (const float*)d_in[3];
    const float* Wk   = (const float*)d_in[4];
    const float* bk   = (const float*)d_in[5];
    const float* Wv   = (const float*)d_in[6];
    const float* bv   = (const float*)d_in[7];
    float* out = (float*)d_out;

    // 0) prep: hidden + W -> fp16 planes
    split_prep<<<PREP_BLOCKS, 256>>>(hid, Wq, Wk, Wv);

    // 1) Q,K,V projections (plain fp16 MMA; fp16 q/k/v + fp32 V)
    qkv_mma<<<dim3(HID_ / 128, BS_ / 128, 3), 256>>>(bq, bk, bv);

    // 2) qq / kk / vv self-similarity scores (fp16 MMA)
    scores_sim<<<dim3(S_ / 128, S_ / 64, 3 * BH_), 256>>>(mask, out + CTX_ELEMS);

    // 3) fused qk scores + softmax + P@V -> scores(qk) region + ctx
    flash_attn<<<dim3(S_ / 64, BH_), 128>>>(mask, out + CTX_ELEMS, out);
}

// round 16
// speedup vs baseline: 1.5889x; 1.0449x over previous
#include <cuda_runtime.h>
#include <cuda_fp16.h>
#include <math.h>
#include <stdint.h>

#define B_   8
#define S_   512
#define HID_ 768
#define H_   12
#define D_   64
#define BS_  (B_*S_)          // 4096
#define BH_  (B_*H_)          // 96

#define CTX_ELEMS ((size_t)B_*S_*HID_)        // 3,145,728
#define SC_ELEMS  ((size_t)BH_*S_*S_)         // 25,165,824

#define NHID ((size_t)BS_*HID_)               // 3,145,728
#define NW   ((size_t)HID_*HID_)              //   589,824

// Scratch (device globals — no allocation in kernel_launch)
__device__ __half g_qh[BH_*S_*D_];            // q,k,v fp16 (roundoff = tf32's)
__device__ __half g_kh[BH_*S_*D_];
__device__ __half g_vh[BH_*S_*D_];            // V [kv][d] for vv scores
__device__ __half g_vt[BH_*S_*D_];            // V^T [d][kv] fp16 for O-phase
__device__ __half g_hidH[NHID];               // hidden: fp16 plane
__device__ __half g_WH[3][NW];                // W: fp16 plane

__device__ __forceinline__ void mma_f16(float* c, const uint32_t* a, const uint32_t* b) {
    asm volatile(
        "mma.sync.aligned.m16n8k16.row.col.f32.f16.f16.f32 "
        "{%0,%1,%2,%3}, {%4,%5,%6,%7}, {%8,%9}, {%0,%1,%2,%3};\n"
        : "+f"(c[0]), "+f"(c[1]), "+f"(c[2]), "+f"(c[3])
        : "r"(a[0]), "r"(a[1]), "r"(a[2]), "r"(a[3]), "r"(b[0]), "r"(b[1]));
}

__device__ __forceinline__ uint32_t smem_u32(const void* p) {
    return (uint32_t)__cvta_generic_to_shared(p);
}

__device__ __forceinline__ void cp16(uint32_t dst, const void* src) {
    asm volatile("cp.async.ca.shared.global [%0], [%1], 16;\n" :: "r"(dst), "l"(src));
}

// ---------------------------------------------------------------------------
// Kernel 0: prep. hidden AND W -> fp16 planes (8 elems/thread). [R14 exact]
// ---------------------------------------------------------------------------
#define PREP_THREADS ((NHID + 3 * NW) / 8)    // 614,400
#define PREP_BLOCKS  (int)(PREP_THREADS / 256) // 2400

__global__ void __launch_bounds__(256)
split_prep(const float* __restrict__ hid, const float* __restrict__ Wq,
           const float* __restrict__ Wk,  const float* __restrict__ Wv)
{
    size_t i = (size_t)blockIdx.x * 256 + threadIdx.x;
    const float* src;
    __half* dst;
    if (i < NHID / 8) {
        size_t base = i * 8;
        src = hid + base;
        dst = g_hidH + base;
    } else {
        size_t j = i - NHID / 8;
        int w = (int)(j / (NW / 8));
        size_t o8 = (j - (size_t)w * (NW / 8)) * 8;
        src = ((w == 0) ? Wq : ((w == 1) ? Wk : Wv)) + o8;
        dst = g_WH[w] + o8;
    }
    float4 v0 = *(const float4*)src;
    float4 v1 = *(const float4*)(src + 4);
    __half2 o[4];
    o[0] = __half2(__float2half_rn(v0.x), __float2half_rn(v0.y));
    o[1] = __half2(__float2half_rn(v0.z), __float2half_rn(v0.w));
    o[2] = __half2(__float2half_rn(v1.x), __float2half_rn(v1.y));
    o[3] = __half2(__float2half_rn(v1.z), __float2half_rn(v1.w));
    *(uint4*)dst = *(uint4*)o;
}

// ---------------------------------------------------------------------------
// Kernel 1: QKV projection via plain fp16 MMA. [R14 loop exact]
// Epilogue: + bias, fp16 q/k/v; V also transposed fp16 [d][kv] for O-phase.
// ---------------------------------------------------------------------------
__global__ void __launch_bounds__(256, 2)
qkv_mma(const float* __restrict__ bq, const float* __restrict__ bk,
        const float* __restrict__ bv)
{
    const int z = blockIdx.z;
    const __half* Wp  = g_WH[z];
    const float* bias = (z == 0) ? bq : ((z == 1) ? bk : bv);
    __half* outh      = (z == 0) ? g_qh : ((z == 1) ? g_kh : g_vh);

    const int m0 = blockIdx.y * 128;
    const int n0 = blockIdx.x * 128;

    __shared__ __align__(16) uint32_t As[2][128][20];
    __shared__ __align__(16) uint32_t Bs[2][128][20];

    const int tid  = threadIdx.x;
    const int lane = tid & 31;
    const int wid  = tid >> 5;
    const int gr   = lane >> 2;
    const int gc   = lane & 3;
    const int wm   = (wid & 1) * 64;
    const int wn   = (wid >> 1) * 32;

    float c[4][4][4];
    #pragma unroll
    for (int im = 0; im < 4; im++)
        #pragma unroll
        for (int jn = 0; jn < 4; jn++)
            #pragma unroll
            for (int r = 0; r < 4; r++) c[im][jn][r] = 0.0f;

    #define LOAD_STAGE(buf, it_)                                                 \
    {                                                                            \
        _Pragma("unroll")                                                        \
        for (int r = 0; r < 2; r++) {                                            \
            int cc = tid + 256 * r; int row = cc >> 2; int sub = cc & 3;         \
            cp16(smem_u32(&As[buf][row][sub * 4]),                               \
                 g_hidH + (size_t)(m0 + row) * HID_ + (it_) * 32 + sub * 8);     \
        }                                                                        \
        _Pragma("unroll")                                                        \
        for (int r = 0; r < 2; r++) {                                            \
            int cc = tid + 256 * r; int row = cc >> 2; int sub = cc & 3;         \
            cp16(smem_u32(&Bs[buf][row][sub * 4]),                               \
                 Wp + (size_t)(n0 + row) * HID_ + (it_) * 32 + sub * 8);         \
        }                                                                        \
        asm volatile("cp.async.commit_group;\n");                                \
    }

    LOAD_STAGE(0, 0)

    const int NIT = HID_ / 32;   // 24 stages of k32
    for (int it = 0; it < NIT; it++) {
        asm volatile("cp.async.wait_group 0;\n");
        __syncthreads();
        if (it + 1 < NIT) { LOAD_STAGE((it + 1) & 1, it + 1) }

        const int buf = it & 1;
        #pragma unroll
        for (int ks = 0; ks < 2; ks++) {
            const int kp = 8 * ks + gc;
            uint32_t a[4][4], b[4][2];
            #pragma unroll
            for (int im = 0; im < 4; im++) {
                int r = wm + im * 16 + gr;
                a[im][0] = As[buf][r    ][kp    ];
                a[im][1] = As[buf][r + 8][kp    ];
                a[im][2] = As[buf][r    ][kp + 4];
                a[im][3] = As[buf][r + 8][kp + 4];
            }
            #pragma unroll
            for (int jn = 0; jn < 4; jn++) {
                int n = wn + jn * 8 + gr;
                b[jn][0] = Bs[buf][n][kp    ];
                b[jn][1] = Bs[buf][n][kp + 4];
            }
            #pragma unroll
            for (int im = 0; im < 4; im++)
                #pragma unroll
                for (int jn = 0; jn < 4; jn++)
                    mma_f16(c[im][jn], a[im], b[jn]);
        }
        __syncthreads();
    }
    #undef LOAD_STAGE

    // Epilogue: + bias; fp16 q/k/v [kv][d]; V also transposed fp16 [d][kv].
    const int h      = (n0 + wn) >> 6;
    const int d_base = (n0 + wn) & 63;
    #pragma unroll
    for (int jn = 0; jn < 4; jn++) {
        int d = d_base + jn * 8 + gc * 2;
        float b0 = bias[n0 + wn + jn * 8 + gc * 2];
        float b1 = bias[n0 + wn + jn * 8 + gc * 2 + 1];
        #pragma unroll
        for (int im = 0; im < 4; im++) {
            int m = m0 + wm + im * 16 + gr;
            int b = m >> 9;
            int s = m & 511;
            size_t base = ((size_t)(b * H_ + h) * S_ + s) * D_ + d;
            float v0 = c[im][jn][0] + b0, v1 = c[im][jn][1] + b1;
            float v2 = c[im][jn][2] + b0, v3 = c[im][jn][3] + b1;
            __half h0 = __float2half_rn(v0), h1 = __float2half_rn(v1);
            __half h2 = __float2half_rn(v2), h3 = __float2half_rn(v3);
            *(__half2*)(outh + base)           = __half2(h0, h1);
            *(__half2*)(outh + base + 8 * D_)  = __half2(h2, h3);
            if (z == 2) {
                size_t tb = ((size_t)(b * H_ + h) * D_ + d) * S_ + s;
                g_vt[tb]           = h0;   // [d  ][s  ]
                g_vt[tb + S_]      = h1;   // [d+1][s  ]
                g_vt[tb + 8]       = h2;   // [d  ][s+8]
                g_vt[tb + S_ + 8]  = h3;   // [d+1][s+8]
            }
        }
    }
}

// ---------------------------------------------------------------------------
// Kernel 2: self-similarity scores (qq, kk, vv) via fp16 m16n8k16. [R14 exact]
// Block: 64(q) x 128(k), 256 threads (8 warps 2x4). grid: (4, 8, 3*96).
// ---------------------------------------------------------------------------
__global__ void __launch_bounds__(256)
scores_sim(const float* __restrict__ mask, float* __restrict__ out_base)
{
    const int z    = blockIdx.z;
    const int type = 1 + z / BH_;       // 1:qq 2:kk 3:vv
    const int bh   = z % BH_;

    const __half* X = (type == 1) ? g_qh : ((type == 2) ? g_kh : g_vh);
    X += (size_t)bh * S_ * D_;

    float* out = out_base + (size_t)type * SC_ELEMS + (size_t)bh * S_ * S_;
    const float* mrow = mask + (size_t)(bh / H_) * S_;

    const int m0 = blockIdx.y * 64;
    const int n0 = blockIdx.x * 128;

    __shared__ __align__(16) uint32_t Xs[64][36];
    __shared__ __align__(16) uint32_t Ys[128][36];

    const int tid = threadIdx.x;

    #pragma unroll
    for (int r = 0; r < 2; r++) {
        int idx = tid + 256 * r;
        int row = idx >> 3;
        int ch  = idx & 7;
        *(uint4*)&Xs[row][ch * 4] =
            *(const uint4*)(X + (size_t)(m0 + row) * D_ + ch * 8);
    }
    #pragma unroll
    for (int r = 0; r < 4; r++) {
        int idx = tid + 256 * r;
        int row = idx >> 3;
        int ch  = idx & 7;
        *(uint4*)&Ys[row][ch * 4] =
            *(const uint4*)(X + (size_t)(n0 + row) * D_ + ch * 8);
    }
    __syncthreads();

    const int lane = tid & 31;
    const int wid  = tid >> 5;
    const int wm   = (wid & 1) * 32;
    const int wn   = (wid >> 1) * 32;
    const int gr   = lane >> 2;
    const int gc   = lane & 3;

    float c[2][4][4];
    #pragma unroll
    for (int im = 0; im < 2; im++)
        #pragma unroll
        for (int jn = 0; jn < 4; jn++)
            #pragma unroll
            for (int r = 0; r < 4; r++) c[im][jn][r] = 0.0f;

    #pragma unroll
    for (int st = 0; st < 4; st++) {
        const int kp = st * 8 + gc;
        uint32_t a[2][4], b[4][2];
        #pragma unroll
        for (int im = 0; im < 2; im++) {
            int r0 = wm + im * 16 + gr;
            a[im][0] = Xs[r0    ][kp    ];
            a[im][1] = Xs[r0 + 8][kp    ];
            a[im][2] = Xs[r0    ][kp + 4];
            a[im][3] = Xs[r0 + 8][kp + 4];
        }
        #pragma unroll
        for (int jn = 0; jn < 4; jn++) {
            int n = wn + jn * 8 + gr;
            b[jn][0] = Ys[n][kp    ];
            b[jn][1] = Ys[n][kp + 4];
        }
        #pragma unroll
        for (int im = 0; im < 2; im++)
            #pragma unroll
            for (int jn = 0; jn < 4; jn++)
                mma_f16(c[im][jn], a[im], b[jn]);
    }

    #pragma unroll
    for (int im = 0; im < 2; im++) {
        #pragma unroll
        for (int jn = 0; jn < 4; jn++) {
            int row = m0 + wm + im * 16 + gr;
            int col = n0 + wn + jn * 8 + gc * 2;
            float mv0 = mrow[col], mv1 = mrow[col + 1];
            float2 o0 = make_float2(c[im][jn][0] * 0.125f + mv0,
                                    c[im][jn][1] * 0.125f + mv1);
            float2 o1 = make_float2(c[im][jn][2] * 0.125f + mv0,
                                    c[im][jn][3] * 0.125f + mv1);
            *(float2*)(out + (size_t)row * S_ + col)       = o0;
            *(float2*)(out + (size_t)(row + 8) * S_ + col) = o1;
        }
    }
}

// ---------------------------------------------------------------------------
// Kernel 3: fused qk-scores + softmax + P@V — all fp16 MMA.
// S-phase: Q,K fp16 (R13-validated). O-phase: P fp16 (mantissa = tf32's,
// zero added error), V^T fp16 tile from g_vt -> 32 MMAs/tile (was 64),
// smem 45KB -> 28KB. 128 threads = 4 warps. grid: (8, 96).
// ---------------------------------------------------------------------------
__global__ void __launch_bounds__(128)
flash_attn(const float* __restrict__ mask, float* __restrict__ sout_base,
           float* __restrict__ ctx)
{
    const int bh = blockIdx.y;
    const int q0 = blockIdx.x * 64;
    const int b  = bh / H_;
    const int h  = bh - b * H_;
    const __half* Qp  = g_qh + (size_t)bh * S_ * D_;
    const __half* Kp  = g_kh + (size_t)bh * S_ * D_;
    const __half* Vtp = g_vt + (size_t)bh * S_ * D_;    // [d][kv]
    float* sout = sout_base + (size_t)bh * S_ * S_;
    const float* mrow = mask + (size_t)b * S_;

    __shared__ __align__(16) uint32_t QPu[64][36];   // Q fp16, then P fp16
    __shared__ __align__(16) uint32_t Ku[64][36];
    __shared__ __align__(16) uint32_t Vtu[64][36];   // V^T [d][kv-pair words]

    const int tid  = threadIdx.x;
    const int lane = tid & 31;
    const int w    = tid >> 5;
    const int gr   = lane >> 2;
    const int gc   = lane & 3;

    #pragma unroll
    for (int r = 0; r < 4; r++) {
        int idx = tid + 128 * r;
        int row = idx >> 3;
        int ch  = idx & 7;
        *(uint4*)&QPu[row][ch * 4] =
            *(const uint4*)(Qp + (size_t)(q0 + row) * D_ + ch * 8);
    }
    __syncthreads();

    uint32_t aq[4][4];
    #pragma unroll
    for (int st = 0; st < 4; st++) {
        int kp = st * 8 + gc;
        int r0 = w * 16 + gr;
        aq[st][0] = QPu[r0    ][kp    ];
        aq[st][1] = QPu[r0 + 8][kp    ];
        aq[st][2] = QPu[r0    ][kp + 4];
        aq[st][3] = QPu[r0 + 8][kp + 4];
    }
    __syncthreads();    // all warps own their aq; QPu free for P reuse

    float o[8][4];
    #pragma unroll
    for (int jd = 0; jd < 8; jd++)
        #pragma unroll
        for (int r = 0; r < 4; r++) o[jd][r] = 0.0f;

    float m0 = -1e30f, m1 = -1e30f, l0 = 0.0f, l1 = 0.0f;
    const int rowg = q0 + w * 16 + gr;

    for (int kt = 0; kt < 8; kt++) {
        // K tile [kv][d] and V^T tile [d][kv]: 512 chunks each, 4/thread
        #pragma unroll
        for (int r = 0; r < 4; r++) {
            int idx = tid + 128 * r;
            int row = idx >> 3;
            int ch  = idx & 7;
            *(uint4*)&Ku[row][ch * 4] =
                *(const uint4*)(Kp + (size_t)(kt*64 + row) * D_ + ch * 8);
            *(uint4*)&Vtu[row][ch * 4] =
                *(const uint4*)(Vtp + (size_t)row * S_ + kt*64 + ch * 8);
        }
        __syncthreads();

        // S = Q @ K^T  (fp16, 4 k16 steps)
        float s[8][4];
        #pragma unroll
        for (int jn = 0; jn < 8; jn++) {
            #pragma unroll
            for (int r = 0; r < 4; r++) s[jn][r] = 0.0f;
            #pragma unroll
            for (int st = 0; st < 4; st++) {
                int kp = st * 8 + gc;
                uint32_t bv[2];
                bv[0] = Ku[jn*8 + gr][kp    ];
                bv[1] = Ku[jn*8 + gr][kp + 4];
                mma_f16(s[jn], aq[st], bv);
            }
        }

        float mx0 = -1e30f, mx1 = -1e30f;
        #pragma unroll
        for (int jn = 0; jn < 8; jn++) {
            int col = kt*64 + jn*8 + gc*2;
            float mv0 = mrow[col], mv1 = mrow[col + 1];
            s[jn][0] = s[jn][0]*0.125f + mv0;  s[jn][1] = s[jn][1]*0.125f + mv1;
            s[jn][2] = s[jn][2]*0.125f + mv0;  s[jn][3] = s[jn][3]*0.125f + mv1;
            *(float2*)(sout + (size_t)rowg       * S_ + col) = make_float2(s[jn][0], s[jn][1]);
            *(float2*)(sout + (size_t)(rowg + 8) * S_ + col) = make_float2(s[jn][2], s[jn][3]);
            mx0 = fmaxf(mx0, fmaxf(s[jn][0], s[jn][1]));
            mx1 = fmaxf(mx1, fmaxf(s[jn][2], s[jn][3]));
        }
        mx0 = fmaxf(mx0, __shfl_xor_sync(0xffffffffu, mx0, 1));
        mx0 = fmaxf(mx0, __shfl_xor_sync(0xffffffffu, mx0, 2));
        mx1 = fmaxf(mx1, __shfl_xor_sync(0xffffffffu, mx1, 1));
        mx1 = fmaxf(mx1, __shfl_xor_sync(0xffffffffu, mx1, 2));

        float mn0 = fmaxf(m0, mx0), mn1 = fmaxf(m1, mx1);
        float sc0 = __expf(m0 - mn0), sc1 = __expf(m1 - mn1);

        // exp + P store (fp16 half2) + row sum
        float ps0 = 0.0f, ps1 = 0.0f;
        #pragma unroll
        for (int jn = 0; jn < 8; jn++) {
            float p0 = __expf(s[jn][0] - mn0), p1 = __expf(s[jn][1] - mn0);
            float p2 = __expf(s[jn][2] - mn1), p3 = __expf(s[jn][3] - mn1);
            ps0 += p0 + p1;  ps1 += p2 + p3;
            int wd = jn*4 + gc;              // kv-pair word (cols 2gc.. within jn*8)
            int r0 = w*16 + gr;
            __half2 hp0 = __half2(__float2half_rn(p0), __float2half_rn(p1));
            __half2 hp1 = __half2(__float2half_rn(p2), __float2half_rn(p3));
            QPu[r0    ][wd] = *(uint32_t*)&hp0;
            QPu[r0 + 8][wd] = *(uint32_t*)&hp1;
        }
        ps0 += __shfl_xor_sync(0xffffffffu, ps0, 1);
        ps0 += __shfl_xor_sync(0xffffffffu, ps0, 2);
        ps1 += __shfl_xor_sync(0xffffffffu, ps1, 1);
        ps1 += __shfl_xor_sync(0xffffffffu, ps1, 2);
        l0 = l0 * sc0 + ps0;  l1 = l1 * sc1 + ps1;
        m0 = mn0;  m1 = mn1;

        #pragma unroll
        for (int jd = 0; jd < 8; jd++) {
            o[jd][0] *= sc0;  o[jd][1] *= sc0;
            o[jd][2] *= sc1;  o[jd][3] *= sc1;
        }
        __syncwarp();   // P written/read only within this warp's rows

        // O += P @ V  (fp16: A = P from QPu, B = V^T from Vtu)
        #pragma unroll
        for (int st = 0; st < 4; st++) {
            int kp = st * 8 + gc;
            uint32_t ap[4];
            int r0 = w*16 + gr;
            ap[0] = QPu[r0    ][kp    ];
            ap[1] = QPu[r0 + 8][kp    ];
            ap[2] = QPu[r0    ][kp + 4];
            ap[3] = QPu[r0 + 8][kp + 4];
            #pragma unroll
            for (int jd = 0; jd < 8; jd++) {
                uint32_t bv[2];
                bv[0] = Vtu[jd*8 + gr][kp    ];
                bv[1] = Vtu[jd*8 + gr][kp + 4];
                mma_f16(o[jd], ap, bv);
            }
        }
        __syncthreads();
    }

    float i0 = 1.0f / l0, i1 = 1.0f / l1;
    #pragma unroll
    for (int jd = 0; jd < 8; jd++) {
        int d = jd*8 + gc*2;
        float* op = ctx + ((size_t)(b * S_ + rowg) * HID_ + h * D_ + d);
        *(float2*)op              = make_float2(o[jd][0] * i0, o[jd][1] * i0);
        *(float2*)(op + 8 * HID_) = make_float2(o[jd][2] * i1, o[jd][3] * i1);
    }
}

// ---------------------------------------------------------------------------
extern "C" void kernel_launch(void* const* d_in, const int* in_sizes, int n_in,
                              void* d_out, int out_size)
{
    const float* hid  = (const float*)d_in[0];
    const float* mask = (const float*)d_in[1];
    const float* Wq   = (const float*)d_in[2];
    const float* bq   = (const float*)d_in[3];
    const float* Wk   = (const float*)d_in[4];
    const float* bk   = (const float*)d_in[5];
    const float* Wv   = (const float*)d_in[6];
    const float* bv   = (const float*)d_in[7];
    float* out = (float*)d_out;

    // 0) prep: hidden + W -> fp16 planes
    split_prep<<<PREP_BLOCKS, 256>>>(hid, Wq, Wk, Wv);

    // 1) Q,K,V projections (fp16 MMA; fp16 q/k/v + transposed fp16 V)
    qkv_mma<<<dim3(HID_ / 128, BS_ / 128, 3), 256>>>(bq, bk, bv);

    // 2) qq / kk / vv self-similarity scores (fp16 MMA)
    scores_sim<<<dim3(S_ / 128, S_ / 64, 3 * BH_), 256>>>(mask, out + CTX_ELEMS);

    // 3) fused qk scores + softmax + P@V (all fp16 MMA) -> scores(qk) + ctx
    flash_attn<<<dim3(S_ / 64, BH_), 128>>>(mask, out + CTX_ELEMS, out);
}